// round 12
// baseline (speedup 1.0000x reference)
#include <cuda_runtime.h>
#include <cuda_bf16.h>
#include <math.h>
#include <stdint.h>

#define BB   64
#define TT   256
#define EE   256
#define HH   1024
#define H3   3072

// Scratch: input projections xw[dir][t][b][j] (includes input bias), ~402MB
__device__ float g_xw[(size_t)2 * TT * BB * H3];
// Hidden state ping-pong: [dir][parity][b][j]
__device__ float g_h[2][2][BB][HH];
// Grid barrier counters, one per direction (monotonic within a launch)
__device__ unsigned int g_bar[2];
// Pre-packed W fragments: [dir][ntile48][tg16][nt8][lane32] uint4 (6MB)
#define PW_SLOTS  (16 * 8 * 32)            // per n-tile: tg x nt x lane
__device__ uint4 g_wpack[2 * 48 * PW_SLOTS];

typedef unsigned long long ull;

// ---------------------------------------------------------------------------
// bf16 split helpers
// ---------------------------------------------------------------------------
static __device__ __forceinline__ unsigned pack_bf16(float a, float b) {
    unsigned short sa = __bfloat16_as_ushort(__float2bfloat16(a));
    unsigned short sb = __bfloat16_as_ushort(__float2bfloat16(b));
    return (unsigned)sa | ((unsigned)sb << 16);
}
static __device__ __forceinline__ float bf16_hi(float a) {
    return __bfloat162float(__float2bfloat16(a));
}

// ---------------------------------------------------------------------------
// MMA / ldmatrix wrappers
// ---------------------------------------------------------------------------
static __device__ __forceinline__ void mma_bf16(float* c, const unsigned* a,
                                                unsigned b0, unsigned b1) {
    asm("mma.sync.aligned.m16n8k16.row.col.f32.bf16.bf16.f32 "
        "{%0,%1,%2,%3}, {%4,%5,%6,%7}, {%8,%9}, {%0,%1,%2,%3};"
        : "+f"(c[0]), "+f"(c[1]), "+f"(c[2]), "+f"(c[3])
        : "r"(a[0]), "r"(a[1]), "r"(a[2]), "r"(a[3]), "r"(b0), "r"(b1));
}
static __device__ __forceinline__ void ldm_x4(unsigned* d, uint32_t addr) {
    asm volatile("ldmatrix.sync.aligned.m8n8.x4.shared.b16 {%0,%1,%2,%3}, [%4];"
        : "=r"(d[0]), "=r"(d[1]), "=r"(d[2]), "=r"(d[3]) : "r"(addr));
}

// ---------------------------------------------------------------------------
// Init hidden state for both directions + reset barrier counters
// ---------------------------------------------------------------------------
__global__ __launch_bounds__(256) void init_h_kernel(const float* __restrict__ hidden) {
    int i = blockIdx.x * blockDim.x + threadIdx.x;   // 0 .. 2*B*H-1
    if (i == 0) { g_bar[0] = 0u; g_bar[1] = 0u; }
    int dir = i / (BB * HH);
    int r   = i % (BB * HH);
    g_h[dir][0][r / HH][r % HH] = hidden[r];
}

// ---------------------------------------------------------------------------
// One-time W fragment pack: W[k][n] (K=256, N=3072) -> B-fragment order,
// bf16 hi/lo splits. Grid (48 n-tiles, 2 dirs). Done ONCE (was per-m-CTA in
// R11 — 128x redundant).
// ---------------------------------------------------------------------------
__global__ __launch_bounds__(256) void pack_w_kernel(
    const float* __restrict__ Wf, const float* __restrict__ Wb)
{
    const int dir = blockIdx.y;
    const float* __restrict__ W = dir ? Wb : Wf;
    const int n0 = blockIdx.x * 64;
    uint4* dst = g_wpack + ((size_t)dir * 48 + blockIdx.x) * PW_SLOTS;

    for (int slot = threadIdx.x; slot < PW_SLOTS; slot += 256) {
        int tg   = slot >> 8;            // /256
        int rem  = slot & 255;
        int nt   = rem >> 5;
        int l    = rem & 31;
        int c    = l & 3;
        int colq = l >> 2;
        int col  = n0 + nt * 8 + colq;
        const float* Wcol = W + col;
        int k0r = tg * 16 + 2 * c;
        float u00 = Wcol[(size_t)(k0r + 0) * H3];
        float u01 = Wcol[(size_t)(k0r + 1) * H3];
        float u10 = Wcol[(size_t)(k0r + 8) * H3];
        float u11 = Wcol[(size_t)(k0r + 9) * H3];
        uint4 v;
        v.x = pack_bf16(u00, u01);
        v.y = pack_bf16(u10, u11);
        v.z = pack_bf16(u00 - bf16_hi(u00), u01 - bf16_hi(u01));
        v.w = pack_bf16(u10 - bf16_hi(u10), u11 - bf16_hi(u11));
        dst[slot] = v;
    }
}

// ---------------------------------------------------------------------------
// Fused embedding + input projection GEMM — bf16 3-term split MMA.
// CTA tile 128m x 64n, full-K A staged once, W staged by coalesced copy from
// the pre-packed global buffer (L2-resident, shared by all 128 m-CTAs).
// ---------------------------------------------------------------------------
#define PA_STRIDE 264   // bf16 elems per A row (528B = 33*16B -> conflict-free ldmatrix)
#define PW_BYTES  (PW_SLOTS * 16)          // 64KB
#define PA_OFF_B  PW_BYTES                 // sA hi byte offset
#define PA_SPLIT_B (128 * PA_STRIDE * 2)   // 67,584B per split
#define PROW_OFF_B (PA_OFF_B + 2 * PA_SPLIT_B)
#define PROJ_SMEM  (PROW_OFF_B + 128 * 4)  // ~201.2KB

__global__ __launch_bounds__(256, 1) void input_proj_kernel(
    const int* __restrict__ x, const float* __restrict__ emb,
    const float* __restrict__ bf, const float* __restrict__ bb)
{
    extern __shared__ char psm[];
    uint4* sW = (uint4*)psm;                                   // fragment-packed W
    unsigned short* sAh = (unsigned short*)(psm + PA_OFF_B);
    unsigned short* sAl = (unsigned short*)(psm + PA_OFF_B + PA_SPLIT_B);
    int* sRow = (int*)(psm + PROW_OFF_B);

    const int dir = blockIdx.z;
    const float* __restrict__ bi = dir ? bb : bf;   // row 0 of b = input bias

    const int m0 = blockIdx.y * 128;
    const int n0 = blockIdx.x * 64;

    const int tid  = threadIdx.x;       // 256
    const int lane = tid & 31;
    const int w    = tid >> 5;          // 0..7
    const int mgroup = w & 3;           // 32 rows each
    const int ngroup = w >> 2;          // 32 cols each

    if (tid < 128) {
        int m = m0 + tid;
        int t = m >> 6;
        int b = m & 63;
        sRow[tid] = x[b * TT + t];
    }
    __syncthreads();

    // ---- Stage pre-packed W tile: plain coalesced uint4 copy (64KB) ----
    {
        const uint4* src = g_wpack + ((size_t)dir * 48 + blockIdx.x) * PW_SLOTS;
        #pragma unroll
        for (int q = 0; q < PW_SLOTS / 256; q++)
            sW[q * 256 + tid] = src[q * 256 + tid];
    }

    // ---- Stage A (gathered emb rows, full K=256) as bf16 hi/lo ----
    {
        int row = tid >> 1;              // 0..127
        int seg = (tid & 1) * 128;       // k base
        const float* src = emb + (size_t)sRow[row] * EE + seg;
        #pragma unroll
        for (int q = 0; q < 32; q++) {
            float4 v = *(const float4*)(src + q * 4);
            float hx = bf16_hi(v.x), hy = bf16_hi(v.y);
            float hz = bf16_hi(v.z), hw = bf16_hi(v.w);
            unsigned hi01 = pack_bf16(v.x, v.y);
            unsigned hi23 = pack_bf16(v.z, v.w);
            unsigned lo01 = pack_bf16(v.x - hx, v.y - hy);
            unsigned lo23 = pack_bf16(v.z - hz, v.w - hw);
            int e = seg + q * 4;
            *(ull*)&sAh[row * PA_STRIDE + e] = (ull)hi01 | ((ull)hi23 << 32);
            *(ull*)&sAl[row * PA_STRIDE + e] = (ull)lo01 | ((ull)lo23 << 32);
        }
    }
    __syncthreads();

    // ---- Compute ----
    float acc[2][4][4] = {};             // [mtile][ntile][frag]

    const int arow0 = (mgroup * 32 + (lane & 15)) * PA_STRIDE;
    const int arow1 = arow0 + 16 * PA_STRIDE;
    const int acol  = (lane >> 4) * 8;
    const uint32_t aH = (uint32_t)__cvta_generic_to_shared(sAh);
    const uint32_t aL = (uint32_t)__cvta_generic_to_shared(sAl);

    #pragma unroll
    for (int tg = 0; tg < 16; tg++) {
        unsigned ahi0[4], alo0[4], ahi1[4], alo1[4];
        int kc = tg * 16 + acol;
        ldm_x4(ahi0, aH + (uint32_t)(arow0 + kc) * 2);
        ldm_x4(alo0, aL + (uint32_t)(arow0 + kc) * 2);
        ldm_x4(ahi1, aH + (uint32_t)(arow1 + kc) * 2);
        ldm_x4(alo1, aL + (uint32_t)(arow1 + kc) * 2);
        #pragma unroll
        for (int nt = 0; nt < 4; nt++) {
            uint4 b = sW[(tg * 8 + ngroup * 4 + nt) * 32 + lane];
            mma_bf16(acc[0][nt], ahi0, b.x, b.y);
            mma_bf16(acc[0][nt], alo0, b.x, b.y);
            mma_bf16(acc[0][nt], ahi0, b.z, b.w);
            mma_bf16(acc[1][nt], ahi1, b.x, b.y);
            mma_bf16(acc[1][nt], alo1, b.x, b.y);
            mma_bf16(acc[1][nt], ahi1, b.z, b.w);
        }
    }

    // ---- Write out (+ input bias) ----
    float* xw = g_xw + ((size_t)dir * TT * BB + m0) * H3;
    #pragma unroll
    for (int mt = 0; mt < 2; mt++) {
        int r0 = mgroup * 32 + mt * 16 + (lane >> 2);
        #pragma unroll
        for (int nt = 0; nt < 4; nt++) {
            int col = ngroup * 32 + nt * 8 + 2 * (lane & 3);
            int n   = n0 + col;
            float b0v = bi[n], b1v = bi[n + 1];
            float2 v0 = make_float2(acc[mt][nt][0] + b0v, acc[mt][nt][1] + b1v);
            float2 v1 = make_float2(acc[mt][nt][2] + b0v, acc[mt][nt][3] + b1v);
            *(float2*)&xw[(size_t)r0 * H3 + n]       = v0;
            *(float2*)&xw[(size_t)(r0 + 8) * H3 + n] = v1;
        }
    }
}

// ---------------------------------------------------------------------------
// Persistent GRU scan kernel — tensor-core (HMMA bf16 split), unchanged R8.
// ---------------------------------------------------------------------------
#define SH_PAD   72                       // bf16 elems per sH row (144B, conflict-free ldmatrix)
#define SUF_BYTES (64 * 6 * 32 * 16)      // 196,608
#define SD_FLOATS (64 * 50)               // 12,800 B
#define SD_OFF_F  (SUF_BYTES / 4)         // float index of sD
#define SH_OFF_B  (SUF_BYTES + SD_FLOATS * 4)              // byte offset of sH
#define SCAN_SMEM (SH_OFF_B + 2 * 64 * SH_PAD * 2)         // 227,840 B

__global__ __launch_bounds__(256, 1) void gru_persistent(
    const float* __restrict__ Uf, const float* __restrict__ bf,
    const float* __restrict__ Ub, const float* __restrict__ bb,
    float* __restrict__ out)
{
    extern __shared__ float smem[];
    uint4* sUf = (uint4*)smem;                          // [t64][ntile6][lane32] 16B
    float* sD  = smem + SD_OFF_F;                       // [64 b][50]
    unsigned short* sH = (unsigned short*)((char*)smem + SH_OFF_B); // [2 split][64 b][SH_PAD]

    const int cta  = blockIdx.x;         // 0..127
    const int dir  = cta >> 6;
    const int j0   = (cta & 63) * 16;

    const float* __restrict__ U    = dir ? Ub : Uf;
    const float* __restrict__ bias = dir ? bb : bf;

    const int tid  = threadIdx.x;        // 256
    const int lane = tid & 31;
    const int w    = tid >> 5;           // 0..7
    const int mtile  = w & 3;            // 16-batch-row tile
    const int nhalf  = w >> 2;           // 3 ntiles each

    const int jl  = tid & 15;
    const int bq  = tid >> 4;            // 0..15
    const int j   = j0 + jl;
    const int b0g = bq * 4;

    // ---- Pre-pack U into B-fragment order (once) ----
    for (int slot = tid; slot < 64 * 6 * 32; slot += 256) {
        int t   = slot / 192;
        int rem = slot % 192;
        int n   = rem >> 5;
        int l   = rem & 31;
        int c    = l & 3;
        int colq = l >> 2;
        int coln = n * 8 + colq;          // 0..47
        int g    = coln >> 4;
        int jc   = coln & 15;
        const float* Ucol = U + (size_t)g * HH + j0 + jc;
        int k0r = t * 16 + 2 * c;
        float u00 = Ucol[(size_t)(k0r + 0) * H3];
        float u01 = Ucol[(size_t)(k0r + 1) * H3];
        float u10 = Ucol[(size_t)(k0r + 8) * H3];
        float u11 = Ucol[(size_t)(k0r + 9) * H3];
        uint4 v;
        v.x = pack_bf16(u00, u01);
        v.y = pack_bf16(u10, u11);
        v.z = pack_bf16(u00 - bf16_hi(u00), u01 - bf16_hi(u01));
        v.w = pack_bf16(u10 - bf16_hi(u10), u11 - bf16_hi(u11));
        sUf[slot] = v;
    }
    const float brz = bias[H3 + j];
    const float brr = bias[H3 + HH + j];
    const float brh = bias[H3 + 2 * HH + j];
    __syncthreads();

    const int sb = tid >> 2;             // 0..63
    const int kb = (tid & 3) * 16;       // 0,16,32,48

    const int arow_hi = (0 * 64 + mtile * 16 + (lane & 15)) * SH_PAD;
    const int arow_lo = (1 * 64 + mtile * 16 + (lane & 15)) * SH_PAD;
    const int acol    = (lane >> 4) * 8;
    const uint32_t sH_base = (uint32_t)__cvta_generic_to_shared(sH);

    unsigned int bar_target = 0;

    for (int s = 0; s < TT; s++) {
        const int p  = s & 1;
        const int tt = dir ? (TT - 1 - s) : s;
        const float* __restrict__ hp = &g_h[dir][p][0][0];
        float* __restrict__ hn       = &g_h[dir][p ^ 1][0][0];
        const float* __restrict__ xw = g_xw + ((size_t)dir * TT + tt) * BB * H3;

        float xz[4], xr[4], xh[4], hprev[4];
        #pragma unroll
        for (int i = 0; i < 4; i++) {
            const float* xwb = xw + (size_t)(b0g + i) * H3;
            xz[i]    = xwb[j];
            xr[i]    = xwb[HH + j];
            xh[i]    = xwb[2 * HH + j];
            hprev[i] = __ldcv(&hp[(size_t)(b0g + i) * HH + j]);
        }

        float acc[3][4] = {};

        float4 pr[4];
        {
            const float* src = hp + (size_t)sb * HH + kb;
            #pragma unroll
            for (int q = 0; q < 4; q++)
                pr[q] = __ldcv((const float4*)(src + q * 4));
        }

        for (int c = 0; c < 16; c++) {
            __syncthreads();
            #pragma unroll
            for (int q = 0; q < 4; q++) {
                float4 v = pr[q];
                float hx = bf16_hi(v.x), hy = bf16_hi(v.y);
                float hz2 = bf16_hi(v.z), hw = bf16_hi(v.w);
                unsigned hi01 = pack_bf16(v.x, v.y);
                unsigned hi23 = pack_bf16(v.z, v.w);
                unsigned lo01 = pack_bf16(v.x - hx, v.y - hy);
                unsigned lo23 = pack_bf16(v.z - hz2, v.w - hw);
                int e = kb + q * 4;
                *(ull*)&sH[(0 * 64 + sb) * SH_PAD + e] = (ull)hi01 | ((ull)hi23 << 32);
                *(ull*)&sH[(1 * 64 + sb) * SH_PAD + e] = (ull)lo01 | ((ull)lo23 << 32);
            }
            __syncthreads();

            if (c < 15) {
                const float* src = hp + (size_t)sb * HH + (c + 1) * 64 + kb;
                #pragma unroll
                for (int q = 0; q < 4; q++)
                    pr[q] = __ldcv((const float4*)(src + q * 4));
            }

            #pragma unroll
            for (int t = 0; t < 4; t++) {
                unsigned ahi[4], alo[4];
                int kc = t * 16 + acol;
                ldm_x4(ahi, sH_base + (uint32_t)(arow_hi + kc) * 2);
                ldm_x4(alo, sH_base + (uint32_t)(arow_lo + kc) * 2);
                int tg = c * 4 + t;
                #pragma unroll
                for (int n = 0; n < 3; n++) {
                    int ntile = nhalf * 3 + n;
                    uint4 bfrag = sUf[(tg * 6 + ntile) * 32 + lane];
                    mma_bf16(acc[n], ahi, bfrag.x, bfrag.y);
                    mma_bf16(acc[n], alo, bfrag.x, bfrag.y);
                    mma_bf16(acc[n], ahi, bfrag.z, bfrag.w);
                }
            }
        }

        {
            int row0 = mtile * 16 + (lane >> 2);
            #pragma unroll
            for (int n = 0; n < 3; n++) {
                int coln = (nhalf * 3 + n) * 8 + 2 * (lane & 3);
                float2 v0 = make_float2(acc[n][0], acc[n][1]);
                float2 v1 = make_float2(acc[n][2], acc[n][3]);
                *(float2*)&sD[row0 * 50 + coln]       = v0;
                *(float2*)&sD[(row0 + 8) * 50 + coln] = v1;
            }
        }
        __syncthreads();

        #pragma unroll
        for (int i = 0; i < 4; i++) {
            int b = b0g + i;
            float az = sD[b * 50 + jl];
            float ar = sD[b * 50 + 16 + jl];
            float ah = sD[b * 50 + 32 + jl];
            float z    = 1.f / (1.f + __expf(-(xz[i] + az + brz)));
            float r    = 1.f / (1.f + __expf(-(xr[i] + ar + brr)));
            float cand = tanhf(xh[i] + r * (ah + brh));
            float v    = z * hprev[i] + (1.f - z) * cand;
            hn[(size_t)b * HH + j] = v;
            out[((size_t)b * TT + tt) * (2 * HH) + dir * HH + j] = v;
            if (s == TT - 1)
                out[(size_t)BB * TT * 2 * HH + ((size_t)dir * BB + b) * HH + j] = v;
        }

        __syncthreads();
        bar_target += 64;
        if (tid == 0) {
            __threadfence();
            atomicAdd(&g_bar[dir], 1u);
            while (*(volatile unsigned int*)&g_bar[dir] < bar_target) {
                __nanosleep(64);
            }
            __threadfence();
        }
        __syncthreads();
    }
}

// ---------------------------------------------------------------------------
// Launch. Inputs (metadata order): x, hidden, emb, Wf, Uf, bf, Wb, Ub, bb.
// Output: concat (B,T,2H) then hf (B,H) then hb (B,H), all float32.
// ---------------------------------------------------------------------------
extern "C" void kernel_launch(void* const* d_in, const int* in_sizes, int n_in,
                              void* d_out, int out_size)
{
    const int*   x      = (const int*)  d_in[0];
    const float* hidden = (const float*)d_in[1];
    const float* emb    = (const float*)d_in[2];
    const float* Wf     = (const float*)d_in[3];
    const float* Uf     = (const float*)d_in[4];
    const float* bf     = (const float*)d_in[5];
    const float* Wb     = (const float*)d_in[6];
    const float* Ub     = (const float*)d_in[7];
    const float* bb     = (const float*)d_in[8];
    float* out = (float*)d_out;

    cudaFuncSetAttribute(gru_persistent,
                         cudaFuncAttributeMaxDynamicSharedMemorySize, SCAN_SMEM);
    cudaFuncSetAttribute(input_proj_kernel,
                         cudaFuncAttributeMaxDynamicSharedMemorySize, PROJ_SMEM);

    init_h_kernel<<<(2 * BB * HH) / 256, 256>>>(hidden);

    // One-time W fragment pack (was per-CTA in R11 — the regression cause)
    {
        dim3 grid(48, 2);
        pack_w_kernel<<<grid, 256>>>(Wf, Wb);
    }

    // Input projections for both directions
    {
        dim3 grid(H3 / 64, (TT * BB) / 128, 2);
        input_proj_kernel<<<grid, 256, PROJ_SMEM>>>(x, emb, bf, bb);
    }

    // Persistent scan: one kernel, 256 internal steps with grid barriers
    gru_persistent<<<128, 256, SCAN_SMEM>>>(Uf, bf, Ub, bb, out);
}

// round 13
// speedup vs baseline: 1.4298x; 1.4298x over previous
#include <cuda_runtime.h>
#include <cuda_bf16.h>
#include <math.h>
#include <stdint.h>

#define BB   64
#define TT   256
#define EE   256
#define HH   1024
#define H3   3072

// Scratch: input projections xw[dir][t][b][j] (includes input bias), ~402MB
__device__ float g_xw[(size_t)2 * TT * BB * H3];
// Hidden state ping-pong: [dir][parity][b][j]
__device__ float g_h[2][2][BB][HH];
// Grid barrier counters, one per direction (monotonic within a launch)
__device__ unsigned int g_bar[2];

typedef unsigned long long ull;

// ---------------------------------------------------------------------------
// bf16 split helpers
// ---------------------------------------------------------------------------
static __device__ __forceinline__ unsigned pack_bf16(float a, float b) {
    unsigned short sa = __bfloat16_as_ushort(__float2bfloat16(a));
    unsigned short sb = __bfloat16_as_ushort(__float2bfloat16(b));
    return (unsigned)sa | ((unsigned)sb << 16);
}
static __device__ __forceinline__ float bf16_hi(float a) {
    return __bfloat162float(__float2bfloat16(a));
}

// ---------------------------------------------------------------------------
// MMA / ldmatrix wrappers
// ---------------------------------------------------------------------------
static __device__ __forceinline__ void mma_bf16(float* c, const unsigned* a,
                                                unsigned b0, unsigned b1) {
    asm("mma.sync.aligned.m16n8k16.row.col.f32.bf16.bf16.f32 "
        "{%0,%1,%2,%3}, {%4,%5,%6,%7}, {%8,%9}, {%0,%1,%2,%3};"
        : "+f"(c[0]), "+f"(c[1]), "+f"(c[2]), "+f"(c[3])
        : "r"(a[0]), "r"(a[1]), "r"(a[2]), "r"(a[3]), "r"(b0), "r"(b1));
}
static __device__ __forceinline__ void ldm_x4(unsigned* d, uint32_t addr) {
    asm volatile("ldmatrix.sync.aligned.m8n8.x4.shared.b16 {%0,%1,%2,%3}, [%4];"
        : "=r"(d[0]), "=r"(d[1]), "=r"(d[2]), "=r"(d[3]) : "r"(addr));
}

// ---------------------------------------------------------------------------
// Init hidden state for both directions + reset barrier counters
// ---------------------------------------------------------------------------
__global__ __launch_bounds__(256) void init_h_kernel(const float* __restrict__ hidden) {
    int i = blockIdx.x * blockDim.x + threadIdx.x;   // 0 .. 2*B*H-1
    if (i == 0) { g_bar[0] = 0u; g_bar[1] = 0u; }
    int dir = i / (BB * HH);
    int r   = i % (BB * HH);
    g_h[dir][0][r / HH][r % HH] = hidden[r];
}

// ---------------------------------------------------------------------------
// Fused embedding + input projection GEMM (exact R8/R7 fp32 version).
// ---------------------------------------------------------------------------
#define SA_STRIDE 132

__global__ __launch_bounds__(256) void input_proj_kernel(
    const int* __restrict__ x, const float* __restrict__ emb,
    const float* __restrict__ Wf, const float* __restrict__ bf,
    const float* __restrict__ Wb, const float* __restrict__ bb)
{
    const int dir = blockIdx.z;
    const float* __restrict__ W  = dir ? Wb : Wf;
    const float* __restrict__ bi = dir ? bb : bf;

    const int m0 = blockIdx.y * 128;
    const int n0 = blockIdx.x * 64;

    __shared__ float sA[16][SA_STRIDE];
    __shared__ float sB[16][64];
    __shared__ int   sRow[128];

    const int tid = threadIdx.x;
    if (tid < 128) {
        int m = m0 + tid;
        int t = m >> 6;
        int b = m & 63;
        sRow[tid] = x[b * TT + t];
    }
    __syncthreads();

    const int am0 = (tid + 0)   >> 2;
    const int akq0 = ((tid + 0)   & 3) * 4;
    const int am1 = (tid + 256) >> 2;
    const int akq1 = ((tid + 256) & 3) * 4;
    const int bkk = tid >> 4;
    const int bnc = (tid & 15) * 4;

    const int ty = tid >> 4;
    const int tx = tid & 15;

    float acc[8][4] = {};
    float4 rA0, rA1, rB;

    rA0 = *(const float4*)&emb[(size_t)sRow[am0] * EE + akq0];
    rA1 = *(const float4*)&emb[(size_t)sRow[am1] * EE + akq1];
    rB  = *(const float4*)&W[(size_t)bkk * H3 + n0 + bnc];

    for (int kc = 0; kc < 16; kc++) {
        __syncthreads();
        sA[akq0 + 0][am0] = rA0.x;
        sA[akq0 + 1][am0] = rA0.y;
        sA[akq0 + 2][am0] = rA0.z;
        sA[akq0 + 3][am0] = rA0.w;
        sA[akq1 + 0][am1] = rA1.x;
        sA[akq1 + 1][am1] = rA1.y;
        sA[akq1 + 2][am1] = rA1.z;
        sA[akq1 + 3][am1] = rA1.w;
        *(float4*)&sB[bkk][bnc] = rB;
        __syncthreads();

        if (kc < 15) {
            int k0 = (kc + 1) * 16;
            rA0 = *(const float4*)&emb[(size_t)sRow[am0] * EE + k0 + akq0];
            rA1 = *(const float4*)&emb[(size_t)sRow[am1] * EE + k0 + akq1];
            rB  = *(const float4*)&W[(size_t)(k0 + bkk) * H3 + n0 + bnc];
        }

        #pragma unroll
        for (int k = 0; k < 16; k++) {
            float4 alo = *(const float4*)&sA[k][ty * 8];
            float4 ahi = *(const float4*)&sA[k][ty * 8 + 4];
            float4 bv  = *(const float4*)&sB[k][tx * 4];
            float a[8] = {alo.x, alo.y, alo.z, alo.w, ahi.x, ahi.y, ahi.z, ahi.w};
            #pragma unroll
            for (int i = 0; i < 8; i++) {
                acc[i][0] += a[i] * bv.x;
                acc[i][1] += a[i] * bv.y;
                acc[i][2] += a[i] * bv.z;
                acc[i][3] += a[i] * bv.w;
            }
        }
    }

    float* xw = g_xw + ((size_t)dir * TT * BB + m0) * H3;
    const int n = n0 + tx * 4;
    const float bi0 = bi[n + 0], bi1 = bi[n + 1], bi2 = bi[n + 2], bi3 = bi[n + 3];
    #pragma unroll
    for (int i = 0; i < 8; i++) {
        int m = ty * 8 + i;
        float4 o;
        o.x = acc[i][0] + bi0;
        o.y = acc[i][1] + bi1;
        o.z = acc[i][2] + bi2;
        o.w = acc[i][3] + bi3;
        *(float4*)&xw[(size_t)m * H3 + n] = o;
    }
}

// ---------------------------------------------------------------------------
// Persistent GRU scan kernel — tensor-core (HMMA bf16 split), R8 +
// next-step xw register prefetch (issued mid k-loop, hides ~577cyc DRAM
// latency of the 12 scattered gate loads per thread per step).
// ---------------------------------------------------------------------------
#define SH_PAD   72                       // bf16 elems per sH row (144B, conflict-free ldmatrix)
#define SUF_BYTES (64 * 6 * 32 * 16)      // 196,608
#define SD_FLOATS (64 * 50)               // 12,800 B
#define SD_OFF_F  (SUF_BYTES / 4)         // float index of sD
#define SH_OFF_B  (SUF_BYTES + SD_FLOATS * 4)              // byte offset of sH
#define SCAN_SMEM (SH_OFF_B + 2 * 64 * SH_PAD * 2)         // 227,840 B

__global__ __launch_bounds__(256, 1) void gru_persistent(
    const float* __restrict__ Uf, const float* __restrict__ bf,
    const float* __restrict__ Ub, const float* __restrict__ bb,
    float* __restrict__ out)
{
    extern __shared__ float smem[];
    uint4* sUf = (uint4*)smem;                          // [t64][ntile6][lane32] 16B
    float* sD  = smem + SD_OFF_F;                       // [64 b][50]
    unsigned short* sH = (unsigned short*)((char*)smem + SH_OFF_B); // [2 split][64 b][SH_PAD]

    const int cta  = blockIdx.x;         // 0..127
    const int dir  = cta >> 6;
    const int j0   = (cta & 63) * 16;

    const float* __restrict__ U    = dir ? Ub : Uf;
    const float* __restrict__ bias = dir ? bb : bf;

    const int tid  = threadIdx.x;        // 256
    const int lane = tid & 31;
    const int w    = tid >> 5;           // 0..7
    const int mtile  = w & 3;            // 16-batch-row tile
    const int nhalf  = w >> 2;           // 3 ntiles each

    const int jl  = tid & 15;
    const int bq  = tid >> 4;            // 0..15
    const int j   = j0 + jl;
    const int b0g = bq * 4;

    // ---- Pre-pack U into B-fragment order (once) ----
    for (int slot = tid; slot < 64 * 6 * 32; slot += 256) {
        int t   = slot / 192;
        int rem = slot % 192;
        int n   = rem >> 5;
        int l   = rem & 31;
        int c    = l & 3;
        int colq = l >> 2;
        int coln = n * 8 + colq;          // 0..47
        int g    = coln >> 4;
        int jc   = coln & 15;
        const float* Ucol = U + (size_t)g * HH + j0 + jc;
        int k0r = t * 16 + 2 * c;
        float u00 = Ucol[(size_t)(k0r + 0) * H3];
        float u01 = Ucol[(size_t)(k0r + 1) * H3];
        float u10 = Ucol[(size_t)(k0r + 8) * H3];
        float u11 = Ucol[(size_t)(k0r + 9) * H3];
        uint4 v;
        v.x = pack_bf16(u00, u01);
        v.y = pack_bf16(u10, u11);
        v.z = pack_bf16(u00 - bf16_hi(u00), u01 - bf16_hi(u01));
        v.w = pack_bf16(u10 - bf16_hi(u10), u11 - bf16_hi(u11));
        sUf[slot] = v;
    }
    const float brz = bias[H3 + j];
    const float brr = bias[H3 + HH + j];
    const float brh = bias[H3 + 2 * HH + j];
    __syncthreads();

    const int sb = tid >> 2;             // 0..63
    const int kb = (tid & 3) * 16;       // 0,16,32,48

    const int arow_hi = (0 * 64 + mtile * 16 + (lane & 15)) * SH_PAD;
    const int arow_lo = (1 * 64 + mtile * 16 + (lane & 15)) * SH_PAD;
    const int acol    = (lane >> 4) * 8;
    const uint32_t sH_base = (uint32_t)__cvta_generic_to_shared(sH);

    unsigned int bar_target = 0;

    // Prefetched next-step xw gate slices
    float nxz[4], nxr[4], nxh[4];
    {
        // Load step 0's xw directly
        const int tt0 = dir ? (TT - 1) : 0;
        const float* xw0 = g_xw + ((size_t)dir * TT + tt0) * BB * H3;
        #pragma unroll
        for (int i = 0; i < 4; i++) {
            const float* xwb = xw0 + (size_t)(b0g + i) * H3;
            nxz[i] = xwb[j];
            nxr[i] = xwb[HH + j];
            nxh[i] = xwb[2 * HH + j];
        }
    }

    for (int s = 0; s < TT; s++) {
        const int p  = s & 1;
        const int tt = dir ? (TT - 1 - s) : s;
        const float* __restrict__ hp = &g_h[dir][p][0][0];
        float* __restrict__ hn       = &g_h[dir][p ^ 1][0][0];

        // This step's gate inputs come from the prefetch registers
        float xz[4], xr[4], xh[4], hprev[4];
        #pragma unroll
        for (int i = 0; i < 4; i++) {
            xz[i] = nxz[i];
            xr[i] = nxr[i];
            xh[i] = nxh[i];
            hprev[i] = __ldcv(&hp[(size_t)(b0g + i) * HH + j]);
        }

        float acc[3][4] = {};

        float4 pr[4];
        {
            const float* src = hp + (size_t)sb * HH + kb;
            #pragma unroll
            for (int q = 0; q < 4; q++)
                pr[q] = __ldcv((const float4*)(src + q * 4));
        }

        for (int c = 0; c < 16; c++) {
            __syncthreads();
            #pragma unroll
            for (int q = 0; q < 4; q++) {
                float4 v = pr[q];
                float hx = bf16_hi(v.x), hy = bf16_hi(v.y);
                float hz2 = bf16_hi(v.z), hw = bf16_hi(v.w);
                unsigned hi01 = pack_bf16(v.x, v.y);
                unsigned hi23 = pack_bf16(v.z, v.w);
                unsigned lo01 = pack_bf16(v.x - hx, v.y - hy);
                unsigned lo23 = pack_bf16(v.z - hz2, v.w - hw);
                int e = kb + q * 4;
                *(ull*)&sH[(0 * 64 + sb) * SH_PAD + e] = (ull)hi01 | ((ull)hi23 << 32);
                *(ull*)&sH[(1 * 64 + sb) * SH_PAD + e] = (ull)lo01 | ((ull)lo23 << 32);
            }
            __syncthreads();

            if (c < 15) {
                const float* src = hp + (size_t)sb * HH + (c + 1) * 64 + kb;
                #pragma unroll
                for (int q = 0; q < 4; q++)
                    pr[q] = __ldcv((const float4*)(src + q * 4));
            }

            // Mid-loop: prefetch NEXT step's xw gate slices (read-only data,
            // safe to hoist across the grid barrier; hides DRAM latency).
            if (c == 8 && s + 1 < TT) {
                const int ttn = dir ? (TT - 2 - s) : (s + 1);
                const float* xwn = g_xw + ((size_t)dir * TT + ttn) * BB * H3;
                #pragma unroll
                for (int i = 0; i < 4; i++) {
                    const float* xwb = xwn + (size_t)(b0g + i) * H3;
                    nxz[i] = xwb[j];
                    nxr[i] = xwb[HH + j];
                    nxh[i] = xwb[2 * HH + j];
                }
            }

            #pragma unroll
            for (int t = 0; t < 4; t++) {
                unsigned ahi[4], alo[4];
                int kc = t * 16 + acol;
                ldm_x4(ahi, sH_base + (uint32_t)(arow_hi + kc) * 2);
                ldm_x4(alo, sH_base + (uint32_t)(arow_lo + kc) * 2);
                int tg = c * 4 + t;
                #pragma unroll
                for (int n = 0; n < 3; n++) {
                    int ntile = nhalf * 3 + n;
                    uint4 bfrag = sUf[(tg * 6 + ntile) * 32 + lane];
                    mma_bf16(acc[n], ahi, bfrag.x, bfrag.y);
                    mma_bf16(acc[n], alo, bfrag.x, bfrag.y);
                    mma_bf16(acc[n], ahi, bfrag.z, bfrag.w);
                }
            }
        }

        {
            int row0 = mtile * 16 + (lane >> 2);
            #pragma unroll
            for (int n = 0; n < 3; n++) {
                int coln = (nhalf * 3 + n) * 8 + 2 * (lane & 3);
                float2 v0 = make_float2(acc[n][0], acc[n][1]);
                float2 v1 = make_float2(acc[n][2], acc[n][3]);
                *(float2*)&sD[row0 * 50 + coln]       = v0;
                *(float2*)&sD[(row0 + 8) * 50 + coln] = v1;
            }
        }
        __syncthreads();

        #pragma unroll
        for (int i = 0; i < 4; i++) {
            int b = b0g + i;
            float az = sD[b * 50 + jl];
            float ar = sD[b * 50 + 16 + jl];
            float ah = sD[b * 50 + 32 + jl];
            float z    = 1.f / (1.f + __expf(-(xz[i] + az + brz)));
            float r    = 1.f / (1.f + __expf(-(xr[i] + ar + brr)));
            float cand = tanhf(xh[i] + r * (ah + brh));
            float v    = z * hprev[i] + (1.f - z) * cand;
            hn[(size_t)b * HH + j] = v;
            out[((size_t)b * TT + tt) * (2 * HH) + dir * HH + j] = v;
            if (s == TT - 1)
                out[(size_t)BB * TT * 2 * HH + ((size_t)dir * BB + b) * HH + j] = v;
        }

        __syncthreads();
        bar_target += 64;
        if (tid == 0) {
            __threadfence();
            atomicAdd(&g_bar[dir], 1u);
            while (*(volatile unsigned int*)&g_bar[dir] < bar_target) {
                __nanosleep(64);
            }
            __threadfence();
        }
        __syncthreads();
    }
}

// ---------------------------------------------------------------------------
// Launch. Inputs (metadata order): x, hidden, emb, Wf, Uf, bf, Wb, Ub, bb.
// Output: concat (B,T,2H) then hf (B,H) then hb (B,H), all float32.
// ---------------------------------------------------------------------------
extern "C" void kernel_launch(void* const* d_in, const int* in_sizes, int n_in,
                              void* d_out, int out_size)
{
    const int*   x      = (const int*)  d_in[0];
    const float* hidden = (const float*)d_in[1];
    const float* emb    = (const float*)d_in[2];
    const float* Wf     = (const float*)d_in[3];
    const float* Uf     = (const float*)d_in[4];
    const float* bf     = (const float*)d_in[5];
    const float* Wb     = (const float*)d_in[6];
    const float* Ub     = (const float*)d_in[7];
    const float* bb     = (const float*)d_in[8];
    float* out = (float*)d_out;

    cudaFuncSetAttribute(gru_persistent,
                         cudaFuncAttributeMaxDynamicSharedMemorySize, SCAN_SMEM);

    init_h_kernel<<<(2 * BB * HH) / 256, 256>>>(hidden);

    {
        dim3 grid(H3 / 64, (TT * BB) / 128, 2);
        input_proj_kernel<<<grid, 256>>>(x, emb, Wf, bf, Wb, bb);
    }

    gru_persistent<<<128, 256, SCAN_SMEM>>>(Uf, bf, Ub, bb, out);
}

// round 16
// speedup vs baseline: 2.1906x; 1.5321x over previous
#include <cuda_runtime.h>
#include <cuda_bf16.h>
#include <math.h>
#include <stdint.h>

#define BB   64
#define TT   256
#define EE   256
#define HH   1024
#define H3   3072

// Scratch: input projections xw[dir][t][b][j] (includes input bias), ~402MB
__device__ float g_xw[(size_t)2 * TT * BB * H3];
// Hidden state ping-pong: [dir][parity][b][j] (fp32, for z*hprev)
__device__ float g_h[2][2][BB][HH];
// Hidden state as bf16 hi/lo splits: [dir][parity][split][b][k] (MMA feed)
__device__ __align__(16) unsigned short g_hbf[2][2][2][BB][HH];
// Grid barrier counters, one per direction (monotonic within a launch)
__device__ unsigned int g_bar[2];

typedef unsigned long long ull;

// ---------------------------------------------------------------------------
// bf16 split helpers
// ---------------------------------------------------------------------------
static __device__ __forceinline__ unsigned pack_bf16(float a, float b) {
    unsigned short sa = __bfloat16_as_ushort(__float2bfloat16(a));
    unsigned short sb = __bfloat16_as_ushort(__float2bfloat16(b));
    return (unsigned)sa | ((unsigned)sb << 16);
}
static __device__ __forceinline__ float bf16_hi(float a) {
    return __bfloat162float(__float2bfloat16(a));
}

// ---------------------------------------------------------------------------
// MMA / ldmatrix wrappers
// ---------------------------------------------------------------------------
static __device__ __forceinline__ void mma_bf16(float* c, const unsigned* a,
                                                unsigned b0, unsigned b1) {
    asm("mma.sync.aligned.m16n8k16.row.col.f32.bf16.bf16.f32 "
        "{%0,%1,%2,%3}, {%4,%5,%6,%7}, {%8,%9}, {%0,%1,%2,%3};"
        : "+f"(c[0]), "+f"(c[1]), "+f"(c[2]), "+f"(c[3])
        : "r"(a[0]), "r"(a[1]), "r"(a[2]), "r"(a[3]), "r"(b0), "r"(b1));
}
static __device__ __forceinline__ void ldm_x4(unsigned* d, uint32_t addr) {
    asm volatile("ldmatrix.sync.aligned.m8n8.x4.shared.b16 {%0,%1,%2,%3}, [%4];"
        : "=r"(d[0]), "=r"(d[1]), "=r"(d[2]), "=r"(d[3]) : "r"(addr));
}
static __device__ __forceinline__ uint4 ldcv_u4(const unsigned short* p) {
    uint4 v;
    asm volatile("ld.global.cv.v4.u32 {%0,%1,%2,%3}, [%4];"
        : "=r"(v.x), "=r"(v.y), "=r"(v.z), "=r"(v.w) : "l"(p));
    return v;
}

// ---------------------------------------------------------------------------
// Init hidden state (fp32 + bf16 splits) + reset barrier counters
// ---------------------------------------------------------------------------
__global__ __launch_bounds__(256) void init_h_kernel(const float* __restrict__ hidden) {
    int i = blockIdx.x * blockDim.x + threadIdx.x;   // 0 .. 2*B*H-1
    if (i == 0) { g_bar[0] = 0u; g_bar[1] = 0u; }
    int dir = i / (BB * HH);
    int r   = i % (BB * HH);
    int b   = r / HH;
    int k   = r % HH;
    float v = hidden[r];
    g_h[dir][0][b][k] = v;
    float hi = bf16_hi(v);
    g_hbf[dir][0][0][b][k] = __bfloat16_as_ushort(__float2bfloat16(v));
    g_hbf[dir][0][1][b][k] = __bfloat16_as_ushort(__float2bfloat16(v - hi));
}

// ---------------------------------------------------------------------------
// Fused embedding + input projection GEMM (exact R7/R8 fp32 version).
// ---------------------------------------------------------------------------
#define SA_STRIDE 132

__global__ __launch_bounds__(256) void input_proj_kernel(
    const int* __restrict__ x, const float* __restrict__ emb,
    const float* __restrict__ Wf, const float* __restrict__ bf,
    const float* __restrict__ Wb, const float* __restrict__ bb)
{
    const int dir = blockIdx.z;
    const float* __restrict__ W  = dir ? Wb : Wf;
    const float* __restrict__ bi = dir ? bb : bf;

    const int m0 = blockIdx.y * 128;
    const int n0 = blockIdx.x * 64;

    __shared__ float sA[16][SA_STRIDE];
    __shared__ float sB[16][64];
    __shared__ int   sRow[128];

    const int tid = threadIdx.x;
    if (tid < 128) {
        int m = m0 + tid;
        int t = m >> 6;
        int b = m & 63;
        sRow[tid] = x[b * TT + t];
    }
    __syncthreads();

    const int am0 = (tid + 0)   >> 2;
    const int akq0 = ((tid + 0)   & 3) * 4;
    const int am1 = (tid + 256) >> 2;
    const int akq1 = ((tid + 256) & 3) * 4;
    const int bkk = tid >> 4;
    const int bnc = (tid & 15) * 4;

    const int ty = tid >> 4;
    const int tx = tid & 15;

    float acc[8][4] = {};
    float4 rA0, rA1, rB;

    rA0 = *(const float4*)&emb[(size_t)sRow[am0] * EE + akq0];
    rA1 = *(const float4*)&emb[(size_t)sRow[am1] * EE + akq1];
    rB  = *(const float4*)&W[(size_t)bkk * H3 + n0 + bnc];

    for (int kc = 0; kc < 16; kc++) {
        __syncthreads();
        sA[akq0 + 0][am0] = rA0.x;
        sA[akq0 + 1][am0] = rA0.y;
        sA[akq0 + 2][am0] = rA0.z;
        sA[akq0 + 3][am0] = rA0.w;
        sA[akq1 + 0][am1] = rA1.x;
        sA[akq1 + 1][am1] = rA1.y;
        sA[akq1 + 2][am1] = rA1.z;
        sA[akq1 + 3][am1] = rA1.w;
        *(float4*)&sB[bkk][bnc] = rB;
        __syncthreads();

        if (kc < 15) {
            int k0 = (kc + 1) * 16;
            rA0 = *(const float4*)&emb[(size_t)sRow[am0] * EE + k0 + akq0];
            rA1 = *(const float4*)&emb[(size_t)sRow[am1] * EE + k0 + akq1];
            rB  = *(const float4*)&W[(size_t)(k0 + bkk) * H3 + n0 + bnc];
        }

        #pragma unroll
        for (int k = 0; k < 16; k++) {
            float4 alo = *(const float4*)&sA[k][ty * 8];
            float4 ahi = *(const float4*)&sA[k][ty * 8 + 4];
            float4 bv  = *(const float4*)&sB[k][tx * 4];
            float a[8] = {alo.x, alo.y, alo.z, alo.w, ahi.x, ahi.y, ahi.z, ahi.w};
            #pragma unroll
            for (int i = 0; i < 8; i++) {
                acc[i][0] += a[i] * bv.x;
                acc[i][1] += a[i] * bv.y;
                acc[i][2] += a[i] * bv.z;
                acc[i][3] += a[i] * bv.w;
            }
        }
    }

    float* xw = g_xw + ((size_t)dir * TT * BB + m0) * H3;
    const int n = n0 + tx * 4;
    const float bi0 = bi[n + 0], bi1 = bi[n + 1], bi2 = bi[n + 2], bi3 = bi[n + 3];
    #pragma unroll
    for (int i = 0; i < 8; i++) {
        int m = ty * 8 + i;
        float4 o;
        o.x = acc[i][0] + bi0;
        o.y = acc[i][1] + bi1;
        o.z = acc[i][2] + bi2;
        o.w = acc[i][3] + bi3;
        *(float4*)&xw[(size_t)m * H3 + n] = o;
    }
}

// ---------------------------------------------------------------------------
// Persistent GRU scan kernel — tensor-core (HMMA bf16 split).
// R8 structure, but h's bf16 hi/lo split is produced ONCE at gate-write time
// (g_hbf); the per-chunk staging is now a pure 16B copy (coalesced LDG.128 +
// conflict-free STS.128) with zero conversion ALU.
// ---------------------------------------------------------------------------
#define SH_PAD   72                       // bf16 elems per sH row (144B, conflict-free ldmatrix)
#define SUF_BYTES (64 * 6 * 32 * 16)      // 196,608
#define SD_FLOATS (64 * 50)               // 12,800 B
#define SD_OFF_F  (SUF_BYTES / 4)         // float index of sD
#define SH_OFF_B  (SUF_BYTES + SD_FLOATS * 4)              // byte offset of sH
#define SCAN_SMEM (SH_OFF_B + 2 * 64 * SH_PAD * 2)         // 227,840 B

__global__ __launch_bounds__(256, 1) void gru_persistent(
    const float* __restrict__ Uf, const float* __restrict__ bf,
    const float* __restrict__ Ub, const float* __restrict__ bb,
    float* __restrict__ out)
{
    extern __shared__ float smem[];
    uint4* sUf = (uint4*)smem;                          // [t64][ntile6][lane32] 16B
    float* sD  = smem + SD_OFF_F;                       // [64 b][50]
    unsigned short* sH = (unsigned short*)((char*)smem + SH_OFF_B); // [2 split][64 b][SH_PAD]

    const int cta  = blockIdx.x;         // 0..127
    const int dir  = cta >> 6;
    const int j0   = (cta & 63) * 16;

    const float* __restrict__ U    = dir ? Ub : Uf;
    const float* __restrict__ bias = dir ? bb : bf;

    const int tid  = threadIdx.x;        // 256
    const int lane = tid & 31;
    const int w    = tid >> 5;           // 0..7
    const int mtile  = w & 3;            // 16-batch-row tile
    const int nhalf  = w >> 2;           // 3 ntiles each

    const int jl  = tid & 15;
    const int bq  = tid >> 4;            // 0..15
    const int j   = j0 + jl;
    const int b0g = bq * 4;

    // ---- Pre-pack U into B-fragment order (once) ----
    for (int slot = tid; slot < 64 * 6 * 32; slot += 256) {
        int t   = slot / 192;
        int rem = slot % 192;
        int n   = rem >> 5;
        int l   = rem & 31;
        int c    = l & 3;
        int colq = l >> 2;
        int coln = n * 8 + colq;          // 0..47
        int g    = coln >> 4;
        int jc   = coln & 15;
        const float* Ucol = U + (size_t)g * HH + j0 + jc;
        int k0r = t * 16 + 2 * c;
        float u00 = Ucol[(size_t)(k0r + 0) * H3];
        float u01 = Ucol[(size_t)(k0r + 1) * H3];
        float u10 = Ucol[(size_t)(k0r + 8) * H3];
        float u11 = Ucol[(size_t)(k0r + 9) * H3];
        uint4 v;
        v.x = pack_bf16(u00, u01);
        v.y = pack_bf16(u10, u11);
        v.z = pack_bf16(u00 - bf16_hi(u00), u01 - bf16_hi(u01));
        v.w = pack_bf16(u10 - bf16_hi(u10), u11 - bf16_hi(u11));
        sUf[slot] = v;
    }
    const float brz = bias[H3 + j];
    const float brr = bias[H3 + HH + j];
    const float brh = bias[H3 + 2 * HH + j];
    __syncthreads();

    // staging mapping: thread -> (batch row sb, 16 k at kb within chunk)
    const int sb = tid >> 2;             // 0..63
    const int kb = (tid & 3) * 16;       // 0,16,32,48

    const int arow_hi = (0 * 64 + mtile * 16 + (lane & 15)) * SH_PAD;
    const int arow_lo = (1 * 64 + mtile * 16 + (lane & 15)) * SH_PAD;
    const int acol    = (lane >> 4) * 8;
    const uint32_t sH_base = (uint32_t)__cvta_generic_to_shared(sH);

    unsigned int bar_target = 0;

    for (int s = 0; s < TT; s++) {
        const int p  = s & 1;
        const int tt = dir ? (TT - 1 - s) : s;
        const float* __restrict__ hp = &g_h[dir][p][0][0];
        float* __restrict__ hn       = &g_h[dir][p ^ 1][0][0];
        const unsigned short* __restrict__ hbH = &g_hbf[dir][p][0][0][0];
        const unsigned short* __restrict__ hbL = &g_hbf[dir][p][1][0][0];
        unsigned short* __restrict__ hbHn = &g_hbf[dir][p ^ 1][0][0][0];
        unsigned short* __restrict__ hbLn = &g_hbf[dir][p ^ 1][1][0][0];
        const float* __restrict__ xw = g_xw + ((size_t)dir * TT + tt) * BB * H3;

        // Gate inputs for this thread's (4 b, 1 j)
        float xz[4], xr[4], xh[4], hprev[4];
        #pragma unroll
        for (int i = 0; i < 4; i++) {
            const float* xwb = xw + (size_t)(b0g + i) * H3;
            xz[i]    = xwb[j];
            xr[i]    = xwb[HH + j];
            xh[i]    = xwb[2 * HH + j];
            hprev[i] = __ldcv(&hp[(size_t)(b0g + i) * HH + j]);
        }

        float acc[3][4] = {};

        // Prefetch h chunk 0 (bf16 hi/lo, 16B vectors, coalesced)
        uint4 ph0, ph1, pl0, pl1;
        {
            const unsigned short* srcH = hbH + (size_t)sb * HH + kb;
            const unsigned short* srcL = hbL + (size_t)sb * HH + kb;
            ph0 = ldcv_u4(srcH);
            ph1 = ldcv_u4(srcH + 8);
            pl0 = ldcv_u4(srcL);
            pl1 = ldcv_u4(srcL + 8);
        }

        for (int c = 0; c < 16; c++) {
            __syncthreads();             // previous chunk MMAs done, sH free
            // Store this chunk (pure copies, no conversion)
            *(uint4*)&sH[(0 * 64 + sb) * SH_PAD + kb]     = ph0;
            *(uint4*)&sH[(0 * 64 + sb) * SH_PAD + kb + 8] = ph1;
            *(uint4*)&sH[(1 * 64 + sb) * SH_PAD + kb]     = pl0;
            *(uint4*)&sH[(1 * 64 + sb) * SH_PAD + kb + 8] = pl1;
            __syncthreads();             // chunk visible

            // Prefetch next chunk while MMAs run
            if (c < 15) {
                const unsigned short* srcH = hbH + (size_t)sb * HH + (c + 1) * 64 + kb;
                const unsigned short* srcL = hbL + (size_t)sb * HH + (c + 1) * 64 + kb;
                ph0 = ldcv_u4(srcH);
                ph1 = ldcv_u4(srcH + 8);
                pl0 = ldcv_u4(srcL);
                pl1 = ldcv_u4(srcL + 8);
            }

            #pragma unroll
            for (int t = 0; t < 4; t++) {
                unsigned ahi[4], alo[4];
                int kc = t * 16 + acol;
                ldm_x4(ahi, sH_base + (uint32_t)(arow_hi + kc) * 2);
                ldm_x4(alo, sH_base + (uint32_t)(arow_lo + kc) * 2);
                int tg = c * 4 + t;
                #pragma unroll
                for (int n = 0; n < 3; n++) {
                    int ntile = nhalf * 3 + n;
                    uint4 bfrag = sUf[(tg * 6 + ntile) * 32 + lane];
                    mma_bf16(acc[n], ahi, bfrag.x, bfrag.y);
                    mma_bf16(acc[n], alo, bfrag.x, bfrag.y);
                    mma_bf16(acc[n], ahi, bfrag.z, bfrag.w);
                }
            }
        }

        {
            int row0 = mtile * 16 + (lane >> 2);
            #pragma unroll
            for (int n = 0; n < 3; n++) {
                int coln = (nhalf * 3 + n) * 8 + 2 * (lane & 3);
                float2 v0 = make_float2(acc[n][0], acc[n][1]);
                float2 v1 = make_float2(acc[n][2], acc[n][3]);
                *(float2*)&sD[row0 * 50 + coln]       = v0;
                *(float2*)&sD[(row0 + 8) * 50 + coln] = v1;
            }
        }
        __syncthreads();

        // Gates + writes (incl. next-step bf16 hi/lo split of h)
        #pragma unroll
        for (int i = 0; i < 4; i++) {
            int b = b0g + i;
            float az = sD[b * 50 + jl];
            float ar = sD[b * 50 + 16 + jl];
            float ah = sD[b * 50 + 32 + jl];
            float z    = 1.f / (1.f + __expf(-(xz[i] + az + brz)));
            float r    = 1.f / (1.f + __expf(-(xr[i] + ar + brr)));
            float cand = tanhf(xh[i] + r * (ah + brh));
            float v    = z * hprev[i] + (1.f - z) * cand;
            hn[(size_t)b * HH + j] = v;
            float vh = bf16_hi(v);
            hbHn[(size_t)b * HH + j] = __bfloat16_as_ushort(__float2bfloat16(v));
            hbLn[(size_t)b * HH + j] = __bfloat16_as_ushort(__float2bfloat16(v - vh));
            out[((size_t)b * TT + tt) * (2 * HH) + dir * HH + j] = v;
            if (s == TT - 1)
                out[(size_t)BB * TT * 2 * HH + ((size_t)dir * BB + b) * HH + j] = v;
        }

        // ---- Grid barrier (per direction) ----
        __syncthreads();
        bar_target += 64;
        if (tid == 0) {
            __threadfence();
            atomicAdd(&g_bar[dir], 1u);
            while (*(volatile unsigned int*)&g_bar[dir] < bar_target) {
                __nanosleep(64);
            }
            __threadfence();
        }
        __syncthreads();
    }
}

// ---------------------------------------------------------------------------
// Launch. Inputs (metadata order): x, hidden, emb, Wf, Uf, bf, Wb, Ub, bb.
// Output: concat (B,T,2H) then hf (B,H) then hb (B,H), all float32.
// ---------------------------------------------------------------------------
extern "C" void kernel_launch(void* const* d_in, const int* in_sizes, int n_in,
                              void* d_out, int out_size)
{
    const int*   x      = (const int*)  d_in[0];
    const float* hidden = (const float*)d_in[1];
    const float* emb    = (const float*)d_in[2];
    const float* Wf     = (const float*)d_in[3];
    const float* Uf     = (const float*)d_in[4];
    const float* bf     = (const float*)d_in[5];
    const float* Wb     = (const float*)d_in[6];
    const float* Ub     = (const float*)d_in[7];
    const float* bb     = (const float*)d_in[8];
    float* out = (float*)d_out;

    cudaFuncSetAttribute(gru_persistent,
                         cudaFuncAttributeMaxDynamicSharedMemorySize, SCAN_SMEM);

    init_h_kernel<<<(2 * BB * HH) / 256, 256>>>(hidden);

    {
        dim3 grid(H3 / 64, (TT * BB) / 128, 2);
        input_proj_kernel<<<grid, 256>>>(x, emb, Wf, bf, Wb, bb);
    }

    gru_persistent<<<128, 256, SCAN_SMEM>>>(Uf, bf, Ub, bb, out);
}

// round 17
// speedup vs baseline: 2.4630x; 1.1244x over previous
#include <cuda_runtime.h>
#include <cuda_bf16.h>
#include <math.h>
#include <stdint.h>

#define BB   64
#define TT   256
#define EE   256
#define HH   1024
#define H3   3072

// Scratch: input projections xw[dir][t][b][j] (includes input bias), ~402MB
__device__ float g_xw[(size_t)2 * TT * BB * H3];
// Hidden state ping-pong: [dir][parity][b][j] (fp32, for z*hprev)
__device__ float g_h[2][2][BB][HH];
// Hidden state as bf16 hi/lo splits: [dir][parity][split][b][k] (MMA feed)
__device__ __align__(16) unsigned short g_hbf[2][2][2][BB][HH];
// Pre-gathered + pre-split embeddings: [m=16384][hi 256 | lo 256] bf16 (16.8MB)
__device__ __align__(16) unsigned short g_ebf[(size_t)16384 * 512];
// Pre-packed W fragments: [dir][ntile48][tg16][nt8][lane32] uint4 (6.3MB)
#define PW_SLOTS  (16 * 8 * 32)
__device__ uint4 g_wpack[2 * 48 * PW_SLOTS];
// Grid barrier counters, one per direction (monotonic within a launch)
__device__ unsigned int g_bar[2];

typedef unsigned long long ull;

// ---------------------------------------------------------------------------
// bf16 split helpers
// ---------------------------------------------------------------------------
static __device__ __forceinline__ unsigned pack_bf16(float a, float b) {
    unsigned short sa = __bfloat16_as_ushort(__float2bfloat16(a));
    unsigned short sb = __bfloat16_as_ushort(__float2bfloat16(b));
    return (unsigned)sa | ((unsigned)sb << 16);
}
static __device__ __forceinline__ float bf16_hi(float a) {
    return __bfloat162float(__float2bfloat16(a));
}

// ---------------------------------------------------------------------------
// MMA / ldmatrix wrappers
// ---------------------------------------------------------------------------
static __device__ __forceinline__ void mma_bf16(float* c, const unsigned* a,
                                                unsigned b0, unsigned b1) {
    asm("mma.sync.aligned.m16n8k16.row.col.f32.bf16.bf16.f32 "
        "{%0,%1,%2,%3}, {%4,%5,%6,%7}, {%8,%9}, {%0,%1,%2,%3};"
        : "+f"(c[0]), "+f"(c[1]), "+f"(c[2]), "+f"(c[3])
        : "r"(a[0]), "r"(a[1]), "r"(a[2]), "r"(a[3]), "r"(b0), "r"(b1));
}
static __device__ __forceinline__ void ldm_x4(unsigned* d, uint32_t addr) {
    asm volatile("ldmatrix.sync.aligned.m8n8.x4.shared.b16 {%0,%1,%2,%3}, [%4];"
        : "=r"(d[0]), "=r"(d[1]), "=r"(d[2]), "=r"(d[3]) : "r"(addr));
}
static __device__ __forceinline__ uint4 ldcv_u4(const unsigned short* p) {
    uint4 v;
    asm volatile("ld.global.cv.v4.u32 {%0,%1,%2,%3}, [%4];"
        : "=r"(v.x), "=r"(v.y), "=r"(v.z), "=r"(v.w) : "l"(p));
    return v;
}

// ---------------------------------------------------------------------------
// Init hidden state (fp32 + bf16 splits) + reset barrier counters
// ---------------------------------------------------------------------------
__global__ __launch_bounds__(256) void init_h_kernel(const float* __restrict__ hidden) {
    int i = blockIdx.x * blockDim.x + threadIdx.x;   // 0 .. 2*B*H-1
    if (i == 0) { g_bar[0] = 0u; g_bar[1] = 0u; }
    int dir = i / (BB * HH);
    int r   = i % (BB * HH);
    int b   = r / HH;
    int k   = r % HH;
    float v = hidden[r];
    g_h[dir][0][b][k] = v;
    float hi = bf16_hi(v);
    g_hbf[dir][0][0][b][k] = __bfloat16_as_ushort(__float2bfloat16(v));
    g_hbf[dir][0][1][b][k] = __bfloat16_as_ushort(__float2bfloat16(v - hi));
}

// ---------------------------------------------------------------------------
// One-time embedding gather + bf16 hi/lo split: g_ebf[m][hi|lo].
// m = t*64 + b (proj row order). Coalesced within emb rows and output.
// ---------------------------------------------------------------------------
__global__ __launch_bounds__(256) void pack_e_kernel(
    const int* __restrict__ x, const float* __restrict__ emb)
{
    int i = blockIdx.x * 256 + threadIdx.x;   // 0 .. 16384*32-1
    int m = i >> 5;
    int c = i & 31;                            // 8-float chunk within row
    int t = m >> 6;
    int b = m & 63;
    int row = x[b * TT + t];
    const float* src = emb + (size_t)row * EE + c * 8;
    float4 v0 = *(const float4*)(src);
    float4 v1 = *(const float4*)(src + 4);
    uint4 hi, lo;
    hi.x = pack_bf16(v0.x, v0.y);
    hi.y = pack_bf16(v0.z, v0.w);
    hi.z = pack_bf16(v1.x, v1.y);
    hi.w = pack_bf16(v1.z, v1.w);
    lo.x = pack_bf16(v0.x - bf16_hi(v0.x), v0.y - bf16_hi(v0.y));
    lo.y = pack_bf16(v0.z - bf16_hi(v0.z), v0.w - bf16_hi(v0.w));
    lo.z = pack_bf16(v1.x - bf16_hi(v1.x), v1.y - bf16_hi(v1.y));
    lo.w = pack_bf16(v1.z - bf16_hi(v1.z), v1.w - bf16_hi(v1.w));
    *(uint4*)&g_ebf[(size_t)m * 512 + c * 8]       = hi;
    *(uint4*)&g_ebf[(size_t)m * 512 + 256 + c * 8] = lo;
}

// ---------------------------------------------------------------------------
// One-time W fragment pack (verified in R12): W[k][n] -> B-fragment order,
// bf16 hi/lo splits. Grid (48 n-tiles, 2 dirs).
// ---------------------------------------------------------------------------
__global__ __launch_bounds__(256) void pack_w_kernel(
    const float* __restrict__ Wf, const float* __restrict__ Wb)
{
    const int dir = blockIdx.y;
    const float* __restrict__ W = dir ? Wb : Wf;
    const int n0 = blockIdx.x * 64;
    uint4* dst = g_wpack + ((size_t)dir * 48 + blockIdx.x) * PW_SLOTS;

    for (int slot = threadIdx.x; slot < PW_SLOTS; slot += 256) {
        int tg   = slot >> 8;
        int rem  = slot & 255;
        int nt   = rem >> 5;
        int l    = rem & 31;
        int c    = l & 3;
        int colq = l >> 2;
        int col  = n0 + nt * 8 + colq;
        const float* Wcol = W + col;
        int k0r = tg * 16 + 2 * c;
        float u00 = Wcol[(size_t)(k0r + 0) * H3];
        float u01 = Wcol[(size_t)(k0r + 1) * H3];
        float u10 = Wcol[(size_t)(k0r + 8) * H3];
        float u11 = Wcol[(size_t)(k0r + 9) * H3];
        uint4 v;
        v.x = pack_bf16(u00, u01);
        v.y = pack_bf16(u10, u11);
        v.z = pack_bf16(u00 - bf16_hi(u00), u01 - bf16_hi(u01));
        v.w = pack_bf16(u10 - bf16_hi(u10), u11 - bf16_hi(u11));
        dst[slot] = v;
    }
}

// ---------------------------------------------------------------------------
// Input projection GEMM — bf16 3-term split MMA, all operands pre-packed.
// CTA tile 128m x 64n; W and A staged by pure coalesced uint4 copies
// (g_wpack / g_ebf). MMA loop identical to R11 (numerics verified).
// ---------------------------------------------------------------------------
#define PA_STRIDE 264   // bf16 elems per A row (528B, conflict-free ldmatrix)
#define PW_BYTES  (PW_SLOTS * 16)          // 64KB
#define PA_OFF_B  PW_BYTES
#define PA_SPLIT_B (128 * PA_STRIDE * 2)   // 67,584B per split
#define PROJ_SMEM  (PA_OFF_B + 2 * PA_SPLIT_B)   // 200,704B

__global__ __launch_bounds__(256, 1) void input_proj_kernel(
    const float* __restrict__ bf, const float* __restrict__ bb)
{
    extern __shared__ char psm[];
    uint4* sW = (uint4*)psm;
    unsigned short* sAh = (unsigned short*)(psm + PA_OFF_B);
    unsigned short* sAl = (unsigned short*)(psm + PA_OFF_B + PA_SPLIT_B);

    const int dir = blockIdx.z;
    const float* __restrict__ bi = dir ? bb : bf;   // row 0 of b = input bias

    const int m0 = blockIdx.y * 128;
    const int n0 = blockIdx.x * 64;

    const int tid  = threadIdx.x;       // 256
    const int lane = tid & 31;
    const int w    = tid >> 5;          // 0..7
    const int mgroup = w & 3;           // 32 rows each
    const int ngroup = w >> 2;          // 32 cols each

    // ---- Stage pre-packed W tile: coalesced uint4 copy (64KB) ----
    {
        const uint4* src = g_wpack + ((size_t)dir * 48 + blockIdx.x) * PW_SLOTS;
        #pragma unroll
        for (int q = 0; q < PW_SLOTS / 256; q++)
            sW[q * 256 + tid] = src[q * 256 + tid];
    }

    // ---- Stage A (pre-split embeddings): coalesced uint4 copy (131KB) ----
    {
        const uint4* srcA = (const uint4*)(g_ebf + (size_t)m0 * 512);
        #pragma unroll
        for (int q = 0; q < 32; q++) {
            int i = q * 256 + tid;           // 0 .. 8191
            int row  = i >> 6;               // 0..127
            int part = i & 63;               // 0-31 hi, 32-63 lo
            uint4 v = srcA[i];
            unsigned short* dst = (part < 32 ? sAh : sAl)
                                  + row * PA_STRIDE + (part & 31) * 8;
            *(uint4*)dst = v;
        }
    }
    __syncthreads();

    // ---- Compute (identical to R11's verified loop) ----
    float acc[2][4][4] = {};             // [mtile][ntile][frag]

    const int arow0 = (mgroup * 32 + (lane & 15)) * PA_STRIDE;
    const int arow1 = arow0 + 16 * PA_STRIDE;
    const int acol  = (lane >> 4) * 8;
    const uint32_t aH = (uint32_t)__cvta_generic_to_shared(sAh);
    const uint32_t aL = (uint32_t)__cvta_generic_to_shared(sAl);

    #pragma unroll
    for (int tg = 0; tg < 16; tg++) {
        unsigned ahi0[4], alo0[4], ahi1[4], alo1[4];
        int kc = tg * 16 + acol;
        ldm_x4(ahi0, aH + (uint32_t)(arow0 + kc) * 2);
        ldm_x4(alo0, aL + (uint32_t)(arow0 + kc) * 2);
        ldm_x4(ahi1, aH + (uint32_t)(arow1 + kc) * 2);
        ldm_x4(alo1, aL + (uint32_t)(arow1 + kc) * 2);
        #pragma unroll
        for (int nt = 0; nt < 4; nt++) {
            uint4 b = sW[(tg * 8 + ngroup * 4 + nt) * 32 + lane];
            mma_bf16(acc[0][nt], ahi0, b.x, b.y);
            mma_bf16(acc[0][nt], alo0, b.x, b.y);
            mma_bf16(acc[0][nt], ahi0, b.z, b.w);
            mma_bf16(acc[1][nt], ahi1, b.x, b.y);
            mma_bf16(acc[1][nt], alo1, b.x, b.y);
            mma_bf16(acc[1][nt], ahi1, b.z, b.w);
        }
    }

    // ---- Write out (+ input bias) ----
    float* xw = g_xw + ((size_t)dir * TT * BB + m0) * H3;
    #pragma unroll
    for (int mt = 0; mt < 2; mt++) {
        int r0 = mgroup * 32 + mt * 16 + (lane >> 2);
        #pragma unroll
        for (int nt = 0; nt < 4; nt++) {
            int col = ngroup * 32 + nt * 8 + 2 * (lane & 3);
            int n   = n0 + col;
            float b0v = bi[n], b1v = bi[n + 1];
            float2 v0 = make_float2(acc[mt][nt][0] + b0v, acc[mt][nt][1] + b1v);
            float2 v1 = make_float2(acc[mt][nt][2] + b0v, acc[mt][nt][3] + b1v);
            *(float2*)&xw[(size_t)r0 * H3 + n]       = v0;
            *(float2*)&xw[(size_t)(r0 + 8) * H3 + n] = v1;
        }
    }
}

// ---------------------------------------------------------------------------
// Persistent GRU scan kernel — tensor-core (HMMA bf16 split), R16 unchanged.
// ---------------------------------------------------------------------------
#define SH_PAD   72
#define SUF_BYTES (64 * 6 * 32 * 16)      // 196,608
#define SD_FLOATS (64 * 50)
#define SD_OFF_F  (SUF_BYTES / 4)
#define SH_OFF_B  (SUF_BYTES + SD_FLOATS * 4)
#define SCAN_SMEM (SH_OFF_B + 2 * 64 * SH_PAD * 2)         // 227,840 B

__global__ __launch_bounds__(256, 1) void gru_persistent(
    const float* __restrict__ Uf, const float* __restrict__ bf,
    const float* __restrict__ Ub, const float* __restrict__ bb,
    float* __restrict__ out)
{
    extern __shared__ float smem[];
    uint4* sUf = (uint4*)smem;
    float* sD  = smem + SD_OFF_F;
    unsigned short* sH = (unsigned short*)((char*)smem + SH_OFF_B);

    const int cta  = blockIdx.x;
    const int dir  = cta >> 6;
    const int j0   = (cta & 63) * 16;

    const float* __restrict__ U    = dir ? Ub : Uf;
    const float* __restrict__ bias = dir ? bb : bf;

    const int tid  = threadIdx.x;
    const int lane = tid & 31;
    const int w    = tid >> 5;
    const int mtile  = w & 3;
    const int nhalf  = w >> 2;

    const int jl  = tid & 15;
    const int bq  = tid >> 4;
    const int j   = j0 + jl;
    const int b0g = bq * 4;

    for (int slot = tid; slot < 64 * 6 * 32; slot += 256) {
        int t   = slot / 192;
        int rem = slot % 192;
        int n   = rem >> 5;
        int l   = rem & 31;
        int c    = l & 3;
        int colq = l >> 2;
        int coln = n * 8 + colq;
        int g    = coln >> 4;
        int jc   = coln & 15;
        const float* Ucol = U + (size_t)g * HH + j0 + jc;
        int k0r = t * 16 + 2 * c;
        float u00 = Ucol[(size_t)(k0r + 0) * H3];
        float u01 = Ucol[(size_t)(k0r + 1) * H3];
        float u10 = Ucol[(size_t)(k0r + 8) * H3];
        float u11 = Ucol[(size_t)(k0r + 9) * H3];
        uint4 v;
        v.x = pack_bf16(u00, u01);
        v.y = pack_bf16(u10, u11);
        v.z = pack_bf16(u00 - bf16_hi(u00), u01 - bf16_hi(u01));
        v.w = pack_bf16(u10 - bf16_hi(u10), u11 - bf16_hi(u11));
        sUf[slot] = v;
    }
    const float brz = bias[H3 + j];
    const float brr = bias[H3 + HH + j];
    const float brh = bias[H3 + 2 * HH + j];
    __syncthreads();

    const int sb = tid >> 2;
    const int kb = (tid & 3) * 16;

    const int arow_hi = (0 * 64 + mtile * 16 + (lane & 15)) * SH_PAD;
    const int arow_lo = (1 * 64 + mtile * 16 + (lane & 15)) * SH_PAD;
    const int acol    = (lane >> 4) * 8;
    const uint32_t sH_base = (uint32_t)__cvta_generic_to_shared(sH);

    unsigned int bar_target = 0;

    for (int s = 0; s < TT; s++) {
        const int p  = s & 1;
        const int tt = dir ? (TT - 1 - s) : s;
        const float* __restrict__ hp = &g_h[dir][p][0][0];
        float* __restrict__ hn       = &g_h[dir][p ^ 1][0][0];
        const unsigned short* __restrict__ hbH = &g_hbf[dir][p][0][0][0];
        const unsigned short* __restrict__ hbL = &g_hbf[dir][p][1][0][0];
        unsigned short* __restrict__ hbHn = &g_hbf[dir][p ^ 1][0][0][0];
        unsigned short* __restrict__ hbLn = &g_hbf[dir][p ^ 1][1][0][0];
        const float* __restrict__ xw = g_xw + ((size_t)dir * TT + tt) * BB * H3;

        float xz[4], xr[4], xh[4], hprev[4];
        #pragma unroll
        for (int i = 0; i < 4; i++) {
            const float* xwb = xw + (size_t)(b0g + i) * H3;
            xz[i]    = xwb[j];
            xr[i]    = xwb[HH + j];
            xh[i]    = xwb[2 * HH + j];
            hprev[i] = __ldcv(&hp[(size_t)(b0g + i) * HH + j]);
        }

        float acc[3][4] = {};

        uint4 ph0, ph1, pl0, pl1;
        {
            const unsigned short* srcH = hbH + (size_t)sb * HH + kb;
            const unsigned short* srcL = hbL + (size_t)sb * HH + kb;
            ph0 = ldcv_u4(srcH);
            ph1 = ldcv_u4(srcH + 8);
            pl0 = ldcv_u4(srcL);
            pl1 = ldcv_u4(srcL + 8);
        }

        for (int c = 0; c < 16; c++) {
            __syncthreads();
            *(uint4*)&sH[(0 * 64 + sb) * SH_PAD + kb]     = ph0;
            *(uint4*)&sH[(0 * 64 + sb) * SH_PAD + kb + 8] = ph1;
            *(uint4*)&sH[(1 * 64 + sb) * SH_PAD + kb]     = pl0;
            *(uint4*)&sH[(1 * 64 + sb) * SH_PAD + kb + 8] = pl1;
            __syncthreads();

            if (c < 15) {
                const unsigned short* srcH = hbH + (size_t)sb * HH + (c + 1) * 64 + kb;
                const unsigned short* srcL = hbL + (size_t)sb * HH + (c + 1) * 64 + kb;
                ph0 = ldcv_u4(srcH);
                ph1 = ldcv_u4(srcH + 8);
                pl0 = ldcv_u4(srcL);
                pl1 = ldcv_u4(srcL + 8);
            }

            #pragma unroll
            for (int t = 0; t < 4; t++) {
                unsigned ahi[4], alo[4];
                int kc = t * 16 + acol;
                ldm_x4(ahi, sH_base + (uint32_t)(arow_hi + kc) * 2);
                ldm_x4(alo, sH_base + (uint32_t)(arow_lo + kc) * 2);
                int tg = c * 4 + t;
                #pragma unroll
                for (int n = 0; n < 3; n++) {
                    int ntile = nhalf * 3 + n;
                    uint4 bfrag = sUf[(tg * 6 + ntile) * 32 + lane];
                    mma_bf16(acc[n], ahi, bfrag.x, bfrag.y);
                    mma_bf16(acc[n], alo, bfrag.x, bfrag.y);
                    mma_bf16(acc[n], ahi, bfrag.z, bfrag.w);
                }
            }
        }

        {
            int row0 = mtile * 16 + (lane >> 2);
            #pragma unroll
            for (int n = 0; n < 3; n++) {
                int coln = (nhalf * 3 + n) * 8 + 2 * (lane & 3);
                float2 v0 = make_float2(acc[n][0], acc[n][1]);
                float2 v1 = make_float2(acc[n][2], acc[n][3]);
                *(float2*)&sD[row0 * 50 + coln]       = v0;
                *(float2*)&sD[(row0 + 8) * 50 + coln] = v1;
            }
        }
        __syncthreads();

        #pragma unroll
        for (int i = 0; i < 4; i++) {
            int b = b0g + i;
            float az = sD[b * 50 + jl];
            float ar = sD[b * 50 + 16 + jl];
            float ah = sD[b * 50 + 32 + jl];
            float z    = 1.f / (1.f + __expf(-(xz[i] + az + brz)));
            float r    = 1.f / (1.f + __expf(-(xr[i] + ar + brr)));
            float cand = tanhf(xh[i] + r * (ah + brh));
            float v    = z * hprev[i] + (1.f - z) * cand;
            hn[(size_t)b * HH + j] = v;
            float vh = bf16_hi(v);
            hbHn[(size_t)b * HH + j] = __bfloat16_as_ushort(__float2bfloat16(v));
            hbLn[(size_t)b * HH + j] = __bfloat16_as_ushort(__float2bfloat16(v - vh));
            out[((size_t)b * TT + tt) * (2 * HH) + dir * HH + j] = v;
            if (s == TT - 1)
                out[(size_t)BB * TT * 2 * HH + ((size_t)dir * BB + b) * HH + j] = v;
        }

        __syncthreads();
        bar_target += 64;
        if (tid == 0) {
            __threadfence();
            atomicAdd(&g_bar[dir], 1u);
            while (*(volatile unsigned int*)&g_bar[dir] < bar_target) {
                __nanosleep(64);
            }
            __threadfence();
        }
        __syncthreads();
    }
}

// ---------------------------------------------------------------------------
// Launch. Inputs (metadata order): x, hidden, emb, Wf, Uf, bf, Wb, Ub, bb.
// Output: concat (B,T,2H) then hf (B,H) then hb (B,H), all float32.
// ---------------------------------------------------------------------------
extern "C" void kernel_launch(void* const* d_in, const int* in_sizes, int n_in,
                              void* d_out, int out_size)
{
    const int*   x      = (const int*)  d_in[0];
    const float* hidden = (const float*)d_in[1];
    const float* emb    = (const float*)d_in[2];
    const float* Wf     = (const float*)d_in[3];
    const float* Uf     = (const float*)d_in[4];
    const float* bf     = (const float*)d_in[5];
    const float* Wb     = (const float*)d_in[6];
    const float* Ub     = (const float*)d_in[7];
    const float* bb     = (const float*)d_in[8];
    float* out = (float*)d_out;

    cudaFuncSetAttribute(gru_persistent,
                         cudaFuncAttributeMaxDynamicSharedMemorySize, SCAN_SMEM);
    cudaFuncSetAttribute(input_proj_kernel,
                         cudaFuncAttributeMaxDynamicSharedMemorySize, PROJ_SMEM);

    init_h_kernel<<<(2 * BB * HH) / 256, 256>>>(hidden);

    // One-time packs: embeddings (gather + split) and W fragments
    pack_e_kernel<<<(16384 * 32) / 256, 256>>>(x, emb);
    {
        dim3 grid(48, 2);
        pack_w_kernel<<<grid, 256>>>(Wf, Wb);
    }

    // Input projections for both directions (MMA, all-coalesced staging)
    {
        dim3 grid(H3 / 64, (TT * BB) / 128, 2);
        input_proj_kernel<<<grid, 256, PROJ_SMEM>>>(bf, bb);
    }

    // Persistent scan: one kernel, 256 internal steps with grid barriers
    gru_persistent<<<128, 256, SCAN_SMEM>>>(Uf, bf, Ub, bb, out);
}